// round 5
// baseline (speedup 1.0000x reference)
#include <cuda_runtime.h>
#include <cstdint>
#include <cstddef>

#define BATCH   64
#define NCAPS   32
#define NROUTES 2048
#define INDIM   16
#define OUTDIM  32
#define NITERS  3
#define THREADS 512
#define NWARPS  16
#define CSZ     4            // cluster size (4 CTAs, same c, consecutive b)
#define CHUNK_ROUTES 16      // routes per stage
#define CHUNK_BYTES  (CHUNK_ROUTES * INDIM * OUTDIM * 4)   // 32768
#define SLICE_BYTES  (CHUNK_BYTES / CSZ)                   // 8192
#define NSTAGES      (NROUTES / CHUNK_ROUTES)              // 128

// ---- SMEM layout (floats) ----
#define SP_STRIDE 33
#define OFF_SP    0                         // 1024 x 33
#define OFF_WB0   (1024 * SP_STRIDE)        // 33792 : W buffer 0 (8192 floats)
#define OFF_WB1   (OFF_WB0 + 8192)          // W buffer 1
#define OFF_VSH   (OFF_WB1 + 8192)
#define OFF_SRED  (OFF_VSH + 32)
#define OFF_WRED  (OFF_SRED + 32)
#define OFF_WVEC  (OFF_WRED + 32)
#define OFF_SCAL  (OFF_WVEC + NWARPS * 32)
#define OFF_MBAR  (OFF_SCAL + 8)            // 4 x u64 (full0, full1, empty0, empty1); even index -> 8B aligned
#define SMEM_FLOATS (OFF_MBAR + 8)
#define SMEM_BYTES  (SMEM_FLOATS * 4)

// ---- PTX helpers ----
__device__ __forceinline__ uint32_t smem_u32(const void* p) {
    uint32_t a;
    asm("{ .reg .u64 t; cvta.to.shared.u64 t, %1; cvt.u32.u64 %0, t; }" : "=r"(a) : "l"(p));
    return a;
}
__device__ __forceinline__ uint32_t ctarank() {
    uint32_t r; asm("mov.u32 %0, %%cluster_ctarank;" : "=r"(r)); return r;
}
#define MBAR_INIT(addr, cnt) \
    asm volatile("mbarrier.init.shared.b64 [%0], %1;" :: "r"(addr), "r"(cnt) : "memory")
#define MBAR_EXPECT_TX(addr, bytes) \
    asm volatile("mbarrier.arrive.expect_tx.shared.b64 _, [%0], %1;" :: "r"(addr), "r"(bytes) : "memory")
#define MBAR_ARRIVE_REMOTE(addr, rk) \
    asm volatile("{ .reg .b32 ra; mapa.shared::cluster.u32 ra, %0, %1; " \
                 "mbarrier.arrive.shared::cluster.b64 _, [ra]; }" \
                 :: "r"(addr), "r"(rk) : "memory")
#define MBAR_WAIT(addr, ph) \
    asm volatile("{ .reg .pred P; WL_%=: " \
                 "mbarrier.try_wait.parity.acquire.cta.shared::cta.b64 P, [%0], %1, 0x989680; " \
                 "@P bra.uni WD_%=; bra.uni WL_%=; WD_%=: }" \
                 :: "r"(addr), "r"(ph) : "memory")
#define BULK_MC(dst, src, sz, mbar, mask) \
    asm volatile("cp.async.bulk.shared::cluster.global.mbarrier::complete_tx::bytes.multicast::cluster " \
                 "[%0], [%1], %2, [%3], %4;" \
                 :: "r"(dst), "l"(src), "r"(sz), "r"(mbar), "h"(mask) : "memory")
#define CLUSTER_SYNC() do { \
    asm volatile("barrier.cluster.arrive.aligned;" ::: "memory"); \
    asm volatile("barrier.cluster.wait.aligned;" ::: "memory"); } while (0)

__global__ void __launch_bounds__(THREADS, 1)
caps_route_kernel(const float* __restrict__ x,
                  const float* __restrict__ W,
                  float* __restrict__ out)
{
    extern __shared__ float sm[];
    float* sp    = sm + OFF_SP;
    float* wbuf0 = sm + OFF_WB0;
    float* wbuf1 = sm + OFF_WB1;
    float* Vsh   = sm + OFF_VSH;
    float* sred  = sm + OFF_SRED;
    float* wred  = sm + OFF_WRED;
    float* wvec  = sm + OFF_WVEC;
    float* scal  = sm + OFF_SCAL;

    const uint32_t mb   = smem_u32(sm + OFF_MBAR);
    const uint32_t full0 = mb, full1 = mb + 8, emp0 = mb + 16, emp1 = mb + 24;
    const uint32_t wb0u = smem_u32(wbuf0), wb1u = smem_u32(wbuf1);

    const int t    = threadIdx.x;
    const int lane = t & 31;
    const int wid  = t >> 5;
    const int b    = blockIdx.x & (BATCH - 1);
    const int c    = blockIdx.x >> 6;
    const uint32_t rank = ctarank();

    const char* Wc = (const char*)(W + (size_t)c * NROUTES * (INDIM * OUTDIM));

    if (t < 32) Vsh[t] = 0.f;

    if (t == 0) {
        MBAR_INIT(full0, 1); MBAR_INIT(full1, 1);
        MBAR_INIT(emp0, CSZ); MBAR_INIT(emp1, CSZ);
    }
    __syncthreads();
    CLUSTER_SYNC();   // all cluster mbarriers live before any multicast

    // Prime stages 0 and 1
    if (t == 0) {
        MBAR_EXPECT_TX(full0, CHUNK_BYTES);
        BULK_MC(wb0u + rank * SLICE_BYTES,
                (const void*)(Wc + 0 * CHUNK_BYTES + rank * SLICE_BYTES),
                SLICE_BYTES, full0, (uint16_t)0xF);
        MBAR_EXPECT_TX(full1, CHUNK_BYTES);
        BULK_MC(wb1u + rank * SLICE_BYTES,
                (const void*)(Wc + 1 * CHUNK_BYTES + rank * SLICE_BYTES),
                SLICE_BYTES, full1, (uint16_t)0xF);
    }

    int fph0 = 0, fph1 = 0;     // full-bar parity cursors (per thread)
    int eph0 = 0, eph1 = 0;     // empty-bar cursors (t==0 only)
    float accA[OUTDIM], accB[OUTDIM];

    // ---------------- Phase 1: staged prior computation ----------------
    for (int gs = 0; gs < NSTAGES; gs++) {
        const int bsel = gs & 1;
        const uint32_t fbar = bsel ? full1 : full0;
        const uint32_t ebar = bsel ? emp1 : emp0;
        const uint32_t wbu  = bsel ? wb1u : wb0u;
        const float* wb     = bsel ? wbuf1 : wbuf0;

        { int ph = bsel ? fph1 : fph0; MBAR_WAIT(fbar, ph); if (bsel) fph1 ^= 1; else fph0 ^= 1; }

        // warp wid computes route r; lane = output column
        const int r = gs * CHUNK_ROUTES + wid;
        const float* wrow = wb + wid * (INDIM * OUTDIM) + lane;   // stride per i: 32 floats
        const float4* xr = reinterpret_cast<const float4*>(x + ((size_t)b * NROUTES + r) * INDIM);
        float a0 = 0.f, a1 = 0.f;
#pragma unroll
        for (int q = 0; q < 4; q++) {
            float4 xq = __ldg(xr + q);
            a0 = fmaf(xq.x, wrow[(4 * q + 0) * 32], a0);
            a1 = fmaf(xq.y, wrow[(4 * q + 1) * 32], a1);
            a0 = fmaf(xq.z, wrow[(4 * q + 2) * 32], a0);
            a1 = fmaf(xq.w, wrow[(4 * q + 3) * 32], a1);
        }
        sp[(size_t)(r & 1023) * SP_STRIDE + lane] = a0 + a1;

        __syncthreads();   // whole CTA done reading this W buffer

        if (t == 0) {
            // free this buffer cluster-wide
            MBAR_ARRIVE_REMOTE(ebar, 0); MBAR_ARRIVE_REMOTE(ebar, 1);
            MBAR_ARRIVE_REMOTE(ebar, 2); MBAR_ARRIVE_REMOTE(ebar, 3);
            if (gs + 2 < NSTAGES) {
                int ph = bsel ? eph1 : eph0; MBAR_WAIT(ebar, ph); if (bsel) eph1 ^= 1; else eph0 ^= 1;
                MBAR_EXPECT_TX(fbar, CHUNK_BYTES);
                BULK_MC(wbu + rank * SLICE_BYTES,
                        (const void*)(Wc + (size_t)(gs + 2) * CHUNK_BYTES + rank * SLICE_BYTES),
                        SLICE_BYTES, fbar, (uint16_t)0xF);
            }
        }

        if (gs == NSTAGES / 2 - 1) {
            // routes 0..1023 complete in sp: pull register copies (routes t, t+512)
            const float* rA = sp + (size_t)t * SP_STRIDE;
            const float* rB = sp + (size_t)(512 + t) * SP_STRIDE;
#pragma unroll
            for (int o = 0; o < OUTDIM; o++) { accA[o] = rA[o]; accB[o] = rB[o]; }
            __syncthreads();   // reads done before second half overwrites sp
        }
    }
    CLUSTER_SYNC();   // drain all remote arrives / bulk traffic before routing

    const float* rowC = sp + (size_t)t * SP_STRIDE;          // route 1024+t
    const float* rowD = sp + (size_t)(512 + t) * SP_STRIDE;  // route 1536+t

    // ---------------- Phase 2: dynamic routing (B_k[n] == p_n . sum_j v_j) ----------------
    for (int it = 0; it < NITERS; it++) {
        float p0, p1, p2, p3;
        if (it == 0) {
            p0 = p1 = p2 = p3 = 1.0f / (float)NROUTES;
        } else {
            float l0 = 0.f, l1 = 0.f, l2 = 0.f, l3 = 0.f;
#pragma unroll
            for (int o = 0; o < OUTDIM; o++) {
                float v = Vsh[o];
                l0 += accA[o] * v;
                l1 += accB[o] * v;
                l2 += rowC[o] * v;
                l3 += rowD[o] * v;
            }
            float m = fmaxf(fmaxf(l0, l1), fmaxf(l2, l3));
#pragma unroll
            for (int s = 16; s; s >>= 1) m = fmaxf(m, __shfl_xor_sync(0xffffffffu, m, s));
            if (lane == 0) wred[wid] = m;
            __syncthreads();
            if (wid == 0) {
                float mm = (lane < 16) ? wred[lane] : -3.402823e38f;
#pragma unroll
                for (int s = 16; s; s >>= 1) mm = fmaxf(mm, __shfl_xor_sync(0xffffffffu, mm, s));
                if (lane == 0) scal[0] = mm;
            }
            __syncthreads();
            const float bmax = scal[0];

            float e0 = __expf(l0 - bmax);
            float e1 = __expf(l1 - bmax);
            float e2 = __expf(l2 - bmax);
            float e3 = __expf(l3 - bmax);
            float zs = e0 + e1 + e2 + e3;
#pragma unroll
            for (int s = 16; s; s >>= 1) zs += __shfl_xor_sync(0xffffffffu, zs, s);
            if (lane == 0) wred[wid] = zs;
            __syncthreads();
            if (wid == 0) {
                float zz = (lane < 16) ? wred[lane] : 0.f;
#pragma unroll
                for (int s = 16; s; s >>= 1) zz += __shfl_xor_sync(0xffffffffu, zz, s);
                if (lane == 0) scal[1] = zz;
            }
            __syncthreads();
            const float invZ = 1.0f / scal[1];
            p0 = e0 * invZ; p1 = e1 * invZ; p2 = e2 * invZ; p3 = e3 * invZ;
        }

        float ps[OUTDIM];
#pragma unroll
        for (int o = 0; o < OUTDIM; o++)
            ps[o] = p0 * accA[o] + p1 * accB[o] + p2 * rowC[o] + p3 * rowD[o];
#pragma unroll
        for (int s = 16; s; s >>= 1) {
#pragma unroll
            for (int o = 0; o < OUTDIM; o++)
                ps[o] += __shfl_xor_sync(0xffffffffu, ps[o], s);
        }
        if (lane == 0) {
#pragma unroll
            for (int o = 0; o < OUTDIM; o++) wvec[wid * 32 + o] = ps[o];
        }
        __syncthreads();
        if (t < 32) {
            float sv = 0.f;
#pragma unroll
            for (int w = 0; w < NWARPS; w++) sv += wvec[w * 32 + t];
            sred[t] = sv;
        }
        __syncthreads();

        if (t < 32) {
            float nr = 0.f;
#pragma unroll
            for (int o = 0; o < OUTDIM; o++) { float sv = sred[o]; nr += sv * sv; }
            float scale = (nr / (1.0f + nr)) * rsqrtf(nr);
            float v = scale * sred[t];
            Vsh[t] += v;
            if (it == NITERS - 1)
                out[((size_t)b * NCAPS + c) * OUTDIM + t] = v;
        }
        __syncthreads();
    }
}

extern "C" void kernel_launch(void* const* d_in, const int* in_sizes, int n_in,
                              void* d_out, int out_size)
{
    const float* x = (const float*)d_in[0];         // [64, 2048, 16]
    const float* W = (const float*)d_in[1];         // [32, 2048, 16, 32]
    float* out = (float*)d_out;                     // [64, 32, 32]

    cudaFuncSetAttribute(caps_route_kernel,
                         cudaFuncAttributeMaxDynamicSharedMemorySize, SMEM_BYTES);

    cudaLaunchConfig_t cfg = {};
    cfg.gridDim = dim3(BATCH * NCAPS);   // bid = c*64 + b : 4 consecutive bids share c
    cfg.blockDim = dim3(THREADS);
    cfg.dynamicSmemBytes = SMEM_BYTES;
    cudaLaunchAttribute attrs[1];
    attrs[0].id = cudaLaunchAttributeClusterDimension;
    attrs[0].val.clusterDim.x = CSZ;
    attrs[0].val.clusterDim.y = 1;
    attrs[0].val.clusterDim.z = 1;
    cfg.attrs = attrs;
    cfg.numAttrs = 1;
    cudaLaunchKernelEx(&cfg, caps_route_kernel, x, W, out);
}

// round 6
// speedup vs baseline: 2.9291x; 2.9291x over previous
#include <cuda_runtime.h>
#include <cuda_fp16.h>
#include <cstddef>
#include <cstdint>

#define BATCH   64
#define NCAPS   32
#define NROUTES 2048
#define INDIM   16
#define OUTDIM  32
#define NITERS  3
#define THREADS 512
#define NWARPS  16

// Prior rows stored as half2[16] with stride 17 (half2 units) -> conflict-free
#define SPH 17

// ---- SMEM layout ----
// sp0 : half2[1024][SPH]  (batch 0, one half of routes)   69632 B
// sp1 : half2[1024][SPH]  (batch 1)                       69632 B
// scratch floats: Vsh[32], sred[32], wred[16], wvec[16*32], scal[4]
#define SP_HALF2S   (1024 * SPH)                 // per batch array, in half2 units
#define OFF_SP0     0                            // in half2 units
#define OFF_SP1     SP_HALF2S
#define OFF_SCRATCH (2 * SP_HALF2S)              // scratch starts here (1 half2 == 1 float slot)
#define N_SCRATCH   (32 + 32 + 16 + NWARPS * 32 + 4)
#define SMEM_BYTES  ((OFF_SCRATCH + N_SCRATCH) * 4)

// Quad-route warp scheme (as R3): lane l -> route (r4 + l/8), cols 4*(l%8)..+3.
// One pass over W feeds BOTH batches' accumulators.
__device__ __forceinline__ void quad2(const float* __restrict__ x,
                                      const float* __restrict__ W,
                                      int b0, int b1, int c, int r4,
                                      int rsub, int c4,
                                      float aX[4], float aY[4])
{
    const int r = r4 + rsub;
    const float4* xr0 = reinterpret_cast<const float4*>(x + ((size_t)b0 * NROUTES + r) * INDIM);
    const float4* xr1 = reinterpret_cast<const float4*>(x + ((size_t)b1 * NROUTES + r) * INDIM);
    const float4* wr  = reinterpret_cast<const float4*>(
        W + ((size_t)c * NROUTES + r) * (INDIM * OUTDIM)) + c4;   // stride per i: 8 float4

    aX[0] = aX[1] = aX[2] = aX[3] = 0.f;
    aY[0] = aY[1] = aY[2] = aY[3] = 0.f;

#pragma unroll
    for (int g = 0; g < 4; g++) {
        float4 xa = __ldg(xr0 + g);
        float4 xb = __ldg(xr1 + g);
        float4 w0 = __ldg(wr + (g * 4 + 0) * 8);
        float4 w1 = __ldg(wr + (g * 4 + 1) * 8);
        float4 w2 = __ldg(wr + (g * 4 + 2) * 8);
        float4 w3 = __ldg(wr + (g * 4 + 3) * 8);

        aX[0] = fmaf(xa.x, w0.x, aX[0]); aX[1] = fmaf(xa.x, w0.y, aX[1]);
        aX[2] = fmaf(xa.x, w0.z, aX[2]); aX[3] = fmaf(xa.x, w0.w, aX[3]);
        aX[0] = fmaf(xa.y, w1.x, aX[0]); aX[1] = fmaf(xa.y, w1.y, aX[1]);
        aX[2] = fmaf(xa.y, w1.z, aX[2]); aX[3] = fmaf(xa.y, w1.w, aX[3]);
        aX[0] = fmaf(xa.z, w2.x, aX[0]); aX[1] = fmaf(xa.z, w2.y, aX[1]);
        aX[2] = fmaf(xa.z, w2.z, aX[2]); aX[3] = fmaf(xa.z, w2.w, aX[3]);
        aX[0] = fmaf(xa.w, w3.x, aX[0]); aX[1] = fmaf(xa.w, w3.y, aX[1]);
        aX[2] = fmaf(xa.w, w3.z, aX[2]); aX[3] = fmaf(xa.w, w3.w, aX[3]);

        aY[0] = fmaf(xb.x, w0.x, aY[0]); aY[1] = fmaf(xb.x, w0.y, aY[1]);
        aY[2] = fmaf(xb.x, w0.z, aY[2]); aY[3] = fmaf(xb.x, w0.w, aY[3]);
        aY[0] = fmaf(xb.y, w1.x, aY[0]); aY[1] = fmaf(xb.y, w1.y, aY[1]);
        aY[2] = fmaf(xb.y, w1.z, aY[2]); aY[3] = fmaf(xb.y, w1.w, aY[3]);
        aY[0] = fmaf(xb.z, w2.x, aY[0]); aY[1] = fmaf(xb.z, w2.y, aY[1]);
        aY[2] = fmaf(xb.z, w2.z, aY[2]); aY[3] = fmaf(xb.z, w2.w, aY[3]);
        aY[0] = fmaf(xb.w, w3.x, aY[0]); aY[1] = fmaf(xb.w, w3.y, aY[1]);
        aY[2] = fmaf(xb.w, w3.z, aY[2]); aY[3] = fmaf(xb.w, w3.w, aY[3]);
    }
}

__global__ void __launch_bounds__(THREADS, 1)
caps_route_kernel(const float* __restrict__ x,
                  const float* __restrict__ W,
                  float* __restrict__ out)
{
    extern __shared__ __half2 smh[];
    __half2* sp0 = smh + OFF_SP0;
    __half2* sp1 = smh + OFF_SP1;
    float* scr  = reinterpret_cast<float*>(smh + OFF_SCRATCH);
    float* Vsh  = scr;            // 32
    float* sred = scr + 32;       // 32
    float* wred = scr + 64;       // 16
    float* wvec = scr + 80;       // 16*32
    float* scal = scr + 80 + NWARPS * 32;  // 4

    const int t    = threadIdx.x;
    const int lane = t & 31;
    const int wid  = t >> 5;
    const int rsub = lane >> 3;
    const int c4   = lane & 7;
    const int bp   = blockIdx.x & (NCAPS - 1);   // 0..31
    const int c    = blockIdx.x >> 5;
    const int b0   = 2 * bp, b1 = 2 * bp + 1;

    // ---------------- Phase 1a: routes 0..1023 ----------------
    {
        const int base = wid * 64;
        for (int j = 0; j < 64; j += 4) {
            float aX[4], aY[4];
            quad2(x, W, b0, b1, c, base + j, rsub, c4, aX, aY);
            const int row = base + j + rsub;
            __half2* r0 = sp0 + (size_t)row * SPH + c4 * 2;
            __half2* r1 = sp1 + (size_t)row * SPH + c4 * 2;
            r0[0] = __floats2half2_rn(aX[0], aX[1]);
            r0[1] = __floats2half2_rn(aX[2], aX[3]);
            r1[0] = __floats2half2_rn(aY[0], aY[1]);
            r1[1] = __floats2half2_rn(aY[2], aY[3]);
        }
    }
    __syncthreads();

    // Pull register copies: batch0 routes t, t+512 ; batch1 routes t, t+512
    __half2 A0[16], B0[16], A1[16], B1[16];
    {
        const __half2* pA0 = sp0 + (size_t)t * SPH;
        const __half2* pB0 = sp0 + (size_t)(512 + t) * SPH;
        const __half2* pA1 = sp1 + (size_t)t * SPH;
        const __half2* pB1 = sp1 + (size_t)(512 + t) * SPH;
#pragma unroll
        for (int j = 0; j < 16; j++) {
            A0[j] = pA0[j]; B0[j] = pB0[j];
            A1[j] = pA1[j]; B1[j] = pB1[j];
        }
    }
    __syncthreads();

    // ---------------- Phase 1b: routes 1024..2047 overwrite ----------------
    {
        const int base = wid * 64;
        for (int j = 0; j < 64; j += 4) {
            float aX[4], aY[4];
            quad2(x, W, b0, b1, c, 1024 + base + j, rsub, c4, aX, aY);
            const int row = base + j + rsub;
            __half2* r0 = sp0 + (size_t)row * SPH + c4 * 2;
            __half2* r1 = sp1 + (size_t)row * SPH + c4 * 2;
            r0[0] = __floats2half2_rn(aX[0], aX[1]);
            r0[1] = __floats2half2_rn(aX[2], aX[3]);
            r1[0] = __floats2half2_rn(aY[0], aY[1]);
            r1[1] = __floats2half2_rn(aY[2], aY[3]);
        }
    }
    __syncthreads();

    // ---------------- Phase 2: routing, batch-sequential ----------------
    for (int bb = 0; bb < 2; bb++) {
        const __half2* A   = bb ? A1 : A0;
        const __half2* B   = bb ? B1 : B0;
        const __half2* spC = (bb ? sp1 : sp0) + (size_t)t * SPH;          // route 1024+t
        const __half2* spD = (bb ? sp1 : sp0) + (size_t)(512 + t) * SPH;  // route 1536+t
        const int bout = bb ? b1 : b0;

        if (t < 32) Vsh[t] = 0.f;
        __syncthreads();

        for (int it = 0; it < NITERS; it++) {
            float p0, p1, p2, p3;
            if (it == 0) {
                p0 = p1 = p2 = p3 = 1.0f / (float)NROUTES;
            } else {
                float l0 = 0.f, l1 = 0.f, l2 = 0.f, l3 = 0.f;
#pragma unroll
                for (int j = 0; j < 16; j++) {
                    float v0 = Vsh[2 * j], v1 = Vsh[2 * j + 1];
                    float2 a = __half22float2(A[j]);
                    float2 b2 = __half22float2(B[j]);
                    float2 cc = __half22float2(spC[j]);
                    float2 dd = __half22float2(spD[j]);
                    l0 += a.x * v0 + a.y * v1;
                    l1 += b2.x * v0 + b2.y * v1;
                    l2 += cc.x * v0 + cc.y * v1;
                    l3 += dd.x * v0 + dd.y * v1;
                }
                float m = fmaxf(fmaxf(l0, l1), fmaxf(l2, l3));
#pragma unroll
                for (int s = 16; s; s >>= 1) m = fmaxf(m, __shfl_xor_sync(0xffffffffu, m, s));
                if (lane == 0) wred[wid] = m;
                __syncthreads();
                if (wid == 0) {
                    float mm = (lane < NWARPS) ? wred[lane] : -3.402823e38f;
#pragma unroll
                    for (int s = 16; s; s >>= 1) mm = fmaxf(mm, __shfl_xor_sync(0xffffffffu, mm, s));
                    if (lane == 0) scal[0] = mm;
                }
                __syncthreads();
                const float bmax = scal[0];

                float e0 = __expf(l0 - bmax);
                float e1 = __expf(l1 - bmax);
                float e2 = __expf(l2 - bmax);
                float e3 = __expf(l3 - bmax);
                float zs = e0 + e1 + e2 + e3;
#pragma unroll
                for (int s = 16; s; s >>= 1) zs += __shfl_xor_sync(0xffffffffu, zs, s);
                if (lane == 0) wred[wid] = zs;
                __syncthreads();
                if (wid == 0) {
                    float zz = (lane < NWARPS) ? wred[lane] : 0.f;
#pragma unroll
                    for (int s = 16; s; s >>= 1) zz += __shfl_xor_sync(0xffffffffu, zz, s);
                    if (lane == 0) scal[1] = zz;
                }
                __syncthreads();
                const float invZ = 1.0f / scal[1];
                p0 = e0 * invZ; p1 = e1 * invZ; p2 = e2 * invZ; p3 = e3 * invZ;
            }

            // s = sum_n probs_n * p_n  (deterministic tree)
            float ps[OUTDIM];
#pragma unroll
            for (int j = 0; j < 16; j++) {
                float2 a = __half22float2(A[j]);
                float2 b2 = __half22float2(B[j]);
                float2 cc = __half22float2(spC[j]);
                float2 dd = __half22float2(spD[j]);
                ps[2 * j]     = p0 * a.x + p1 * b2.x + p2 * cc.x + p3 * dd.x;
                ps[2 * j + 1] = p0 * a.y + p1 * b2.y + p2 * cc.y + p3 * dd.y;
            }
#pragma unroll
            for (int s = 16; s; s >>= 1) {
#pragma unroll
                for (int o = 0; o < OUTDIM; o++)
                    ps[o] += __shfl_xor_sync(0xffffffffu, ps[o], s);
            }
            if (lane == 0) {
#pragma unroll
                for (int o = 0; o < OUTDIM; o++) wvec[wid * 32 + o] = ps[o];
            }
            __syncthreads();
            if (t < 32) {
                float sv = 0.f;
#pragma unroll
                for (int w = 0; w < NWARPS; w++) sv += wvec[w * 32 + t];
                sred[t] = sv;
            }
            __syncthreads();

            if (t < 32) {
                float nr = 0.f;
#pragma unroll
                for (int o = 0; o < OUTDIM; o++) { float sv = sred[o]; nr += sv * sv; }
                float scale = (nr / (1.0f + nr)) * rsqrtf(nr);
                float v = scale * sred[t];
                Vsh[t] += v;
                if (it == NITERS - 1)
                    out[((size_t)bout * NCAPS + c) * OUTDIM + t] = v;
            }
            __syncthreads();
        }
    }
}

extern "C" void kernel_launch(void* const* d_in, const int* in_sizes, int n_in,
                              void* d_out, int out_size)
{
    const float* x = (const float*)d_in[0];         // [64, 2048, 16]
    const float* W = (const float*)d_in[1];         // [32, 2048, 16, 32]
    float* out = (float*)d_out;                     // [64, 32, 32]

    cudaFuncSetAttribute(caps_route_kernel,
                         cudaFuncAttributeMaxDynamicSharedMemorySize, SMEM_BYTES);

    dim3 grid(NCAPS * (BATCH / 2));   // bid = c*32 + bp ; each CTA does batches 2bp, 2bp+1
    caps_route_kernel<<<grid, THREADS, SMEM_BYTES>>>(x, W, out);
}